// round 10
// baseline (speedup 1.0000x reference)
#include <cuda_runtime.h>

// ---------------------------------------------------------------------------
// PatchCRPS:  mean( (sort(unfold9(pred - avg9(pred))) -
//                    sort(unfold9(targ - avg9(targ))))^2 )
// Shapes: (8,1,256,256) fp32.  K=9, P=4, count_include_pad=False.
//
// R10 = R9 with dual-pipe CE rebalanced for the measured 6-op arithmetic CE
// (fabsf does not fold): f = 1/4 of CEs on the fma pipe -> per-pipe 1.5
// ops/CE -> CE stream ~0.75x. Same mix applied to the column sorts.
// ---------------------------------------------------------------------------

#define B 8
#define H 256
#define W 256
#define NPIX (B * H * W)           // 524288
#define NBLKM (2 * B * H)          // 4096 main blocks (half-row each)
#define NTOT 42467328.0            // B*H*W*81

// Scratch (device globals — no allocation)
__device__ float g_dist[2][NPIX];      // x - avgpool9(x)
__device__ float g_partial[NBLKM];     // per-block partial sums

// ---------------------------------------------------------------------------
// Compare-exchange, two flavors:
//   alu:  FMNMX pair (2 alu ops)
//   fma:  min,max = (p+q)/2 -/+ |p-q|/2  (~6 fma ops incl. non-folded FABS)
// ---------------------------------------------------------------------------
__device__ __forceinline__ void ce_alu(float& p, float& q) {
    float a = p, b = q;
    p = fminf(a, b);
    q = fmaxf(a, b);
}
__device__ __forceinline__ void ce_fma(float& p, float& q) {
    float a = p, b = q;
    float d  = a - b;                  // FADD
    float hd = d * 0.5f;               // FMUL
    float hs = __fmaf_rn(d, 0.5f, b);  // FFMA = (p+q)/2
    float ad = fabsf(hd);
    p = hs - ad;                       // FADD
    q = hs + ad;                       // FADD
}

// ---------------------------------------------------------------------------
// Column sorter: Batcher network for n=16 pruned to 9 wires (wires>=9 = +inf).
// ---------------------------------------------------------------------------
struct Net9 {
    int lo[64]; int hi[64]; int n;
    constexpr Net9() : lo(), hi(), n(0) {
        for (int p = 1; p < 16; p <<= 1)
            for (int k = p; k >= 1; k >>= 1)
                for (int j = k % p; j + k < 16; j += 2 * k)
                    for (int i = 0; i < k; i++) {
                        int a = i + j, b = i + j + k;
                        if (b < 9 && (a / (2 * p)) == (b / (2 * p))) {
                            lo[n] = a; hi[n] = b; n++;
                        }
                    }
    }
};
__device__ constexpr Net9 N9;

template <int I>
__device__ __forceinline__ void apply9(float (&v)[9]) {
    if constexpr (I < N9.n) {
        constexpr int a = N9.lo[I];
        constexpr int b = N9.hi[I];
        if constexpr ((I % 4) == 0) ce_fma(v[a], v[b]);
        else                        ce_alu(v[a], v[b]);
        apply9<I + 1>(v);
    }
}
__device__ __forceinline__ void sort9(float (&v)[9]) { apply9<0>(v); }

// ---------------------------------------------------------------------------
// Merge network: 256-wire Batcher, phases p>=16 only (16-blocks pre-sorted:
// sorted column of 9 + 7x +inf pad; columns 9..15 all +inf). Exact pruning by
// constexpr always-inf simulation: b-inf -> pruned; a-inf -> MOV a<-b.
// Pad wires never read before first write. Result: wires 0..80 sorted.
// ---------------------------------------------------------------------------
struct MergeNet {
    short a[2048]; short b[2048]; short mv[2048]; int n;
    constexpr MergeNet() : a(), b(), mv(), n(0) {
        bool inf[256] = {};
        for (int c = 0; c < 16; c++)
            for (int i = 0; i < 16; i++)
                inf[c * 16 + i] = (c >= 9) || (i >= 9);
        for (int p = 16; p < 256; p <<= 1)
            for (int k = p; k >= 1; k >>= 1)
                for (int j = k % p; j + k < 256; j += 2 * k)
                    for (int i = 0; i < k; i++) {
                        int x = i + j, y = i + j + k;
                        if ((x / (2 * p)) != (y / (2 * p))) continue;
                        if (inf[y]) continue;              // no-op
                        if (inf[x]) {                       // MOV x<-y
                            a[n] = (short)x; b[n] = (short)y; mv[n] = 1; n++;
                            inf[x] = false; inf[y] = true;
                        } else {
                            a[n] = (short)x; b[n] = (short)y; mv[n] = 0; n++;
                        }
                    }
    }
};
__device__ constexpr MergeNet MN;

template <int I, int T>
__device__ __forceinline__ void mergeChunk(float (&v)[144]) {
    if constexpr (T > 0 && I < MN.n) {
        constexpr int x = MN.a[I];
        constexpr int y = MN.b[I];
        if constexpr (MN.mv[I] != 0) {
            v[x] = v[y];
        } else if constexpr ((I % 4) == 0) {
            ce_fma(v[x], v[y]);
        } else {
            ce_alu(v[x], v[y]);
        }
        mergeChunk<I + 1, T - 1>(v);
    }
}
template <int I>
__device__ __forceinline__ void mergeAll(float (&v)[144]) {
    if constexpr (I < MN.n) {
        mergeChunk<I, 32>(v);
        mergeAll<I + 32>(v);
    }
}
__device__ __forceinline__ void merge81(float (&v)[144]) { mergeAll<0>(v); }

// ---------------------------------------------------------------------------
// Fused prologue: block = (tensor, batch, 8-row strip). Loads 16 rows (with
// halo) into SMEM, 16 rows of horizontal 9-sums, then 8 rows of
// dist = x - boxsum/validcount straight to g_dist. 33 KB SMEM, 512 blocks.
// ---------------------------------------------------------------------------
__global__ __launch_bounds__(256) void prologue_kernel(
        const float* __restrict__ pred, const float* __restrict__ targ) {
    __shared__ float raw[16][264];   // 4 zero pad each side
    __shared__ float hs[16][256];    // horizontal 9-sums

    int tid = threadIdx.x;
    int t   = blockIdx.x >> 8;
    int b   = (blockIdx.x >> 5) & 7;
    int s   = blockIdx.x & 31;
    int r0  = s * 8;
    const float* __restrict__ src = t ? targ : pred;
    int ibase = b * 65536;

#pragma unroll
    for (int r = 0; r < 16; r++) {
        int gr = r0 - 4 + r;
        raw[r][tid + 4] = ((unsigned)gr < 256u) ? src[ibase + gr * 256 + tid] : 0.f;
    }
    if (tid < 4) {
#pragma unroll
        for (int r = 0; r < 16; r++) { raw[r][tid] = 0.f; raw[r][260 + tid] = 0.f; }
    }
    __syncthreads();

#pragma unroll
    for (int r = 0; r < 16; r++) {
        float a = 0.f;
#pragma unroll
        for (int i = 0; i < 9; i++) a += raw[r][tid + i];
        hs[r][tid] = a;
    }
    __syncthreads();

    int cw = min(tid + 4, 255) - max(tid - 4, 0) + 1;
#pragma unroll
    for (int k = 0; k < 8; k++) {
        int h  = r0 + k;
        int lr = k + 4;
        float vs = 0.f;
#pragma unroll
        for (int j = -4; j <= 4; j++) vs += hs[lr + j][tid];
        int ch = min(h + 4, 255) - max(h - 4, 0) + 1;
        g_dist[t][ibase + h * 256 + tid] = raw[lr][tid + 4] - vs / (float)(ch * cw);
    }
}

// ---------------------------------------------------------------------------
// Main kernel: block = (batch, row, half). 256 threads: lane pair (2k,2k+1)
// = (pred, targ) of pixel w0+k. Column sorts -> interleaved SMEM -> gather 9
// sorted columns -> merge network -> diff via shfl_xor(1) -> partial store.
// ---------------------------------------------------------------------------
__global__ __launch_bounds__(256, 1) void patchcrps_kernel() {
    __shared__ float scol[9][280];   // interleaved: col c of tensor t at [i][2c+t]
    __shared__ float ws[8];

    int tid = threadIdx.x;
    int t   = tid & 1;               // 0=pred, 1=targ
    int wl  = tid >> 1;              // 0..127 pixel-in-half
    int r   = blockIdx.x & 1;
    int h   = (blockIdx.x >> 1) & 255;
    int b   = blockIdx.x >> 9;
    int w0  = r * 128;
    int ibase = b * 65536;

    const float* __restrict__ src = g_dist[t];

    // ---- 1. column sorts: thread tid -> (t, c=wl); tid<16 also c=128+wl ----
    {
        float col[9];
        int wc = w0 - 4 + wl;
        bool cv = (unsigned)wc < 256u;
#pragma unroll
        for (int i = 0; i < 9; i++) {
            int hh = h - 4 + i;
            col[i] = (cv && (unsigned)hh < 256u) ? src[ibase + hh * 256 + wc] : 0.f;
        }
        sort9(col);
#pragma unroll
        for (int i = 0; i < 9; i++) scol[i][tid] = col[i];
    }
    if (tid < 16) {
        float col[9];
        int wc = w0 + 124 + wl;      // columns w0+124..w0+131
        bool cv = (unsigned)wc < 256u;
#pragma unroll
        for (int i = 0; i < 9; i++) {
            int hh = h - 4 + i;
            col[i] = (cv && (unsigned)hh < 256u) ? src[ibase + hh * 256 + wc] : 0.f;
        }
        sort9(col);
#pragma unroll
        for (int i = 0; i < 9; i++) scol[i][256 + tid] = col[i];
    }
    __syncthreads();

    // ---- 2. gather 9 sorted columns into 16-spaced wires (conflict-free) ----
    float v[144];
#pragma unroll
    for (int dx = 0; dx < 9; dx++)
#pragma unroll
        for (int i = 0; i < 9; i++)
            v[dx * 16 + i] = scol[i][tid + 2 * dx];

    // ---- 3. merge: sorted 81 ends in wires 0..80 ----
    merge81(v);

    // ---- 4. sorted diff via pair shuffle; both lanes accumulate same d^2 ----
    float acc = 0.f;
#pragma unroll
    for (int i = 0; i < 81; i++) {
        float o = __shfl_xor_sync(0xffffffffu, v[i], 1);
        float d = v[i] - o;
        acc += d * d;
    }

    // ---- 5. block reduction (deterministic) + partial store; exit ----
#pragma unroll
    for (int off = 16; off; off >>= 1)
        acc += __shfl_xor_sync(0xffffffffu, acc, off);
    if ((tid & 31) == 0) ws[tid >> 5] = acc;
    __syncthreads();
    if (tid == 0) {
        float s = 0.f;
#pragma unroll
        for (int k = 0; k < 8; k++) s += ws[k];
        g_partial[blockIdx.x] = s;
    }
}

// ---------------------------------------------------------------------------
// Finalize: fixed-order double reduction of 4096 partials (1 block).
// ---------------------------------------------------------------------------
__global__ __launch_bounds__(512) void finalize_kernel(float* __restrict__ out) {
    __shared__ double sh[512];
    int tid = threadIdx.x;
    double s = 0.0;
#pragma unroll
    for (int e = 0; e < 8; e++) s += (double)g_partial[tid * 8 + e];
    sh[tid] = s;
    __syncthreads();
    for (int off = 256; off; off >>= 1) {
        if (tid < off) sh[tid] += sh[tid + off];
        __syncthreads();
    }
    if (tid == 0) out[0] = (float)(sh[0] / (2.0 * NTOT));
}

// ---------------------------------------------------------------------------
extern "C" void kernel_launch(void* const* d_in, const int* in_sizes, int n_in,
                              void* d_out, int out_size) {
    const float* pred = (const float*)d_in[0];
    const float* targ = (const float*)d_in[1];
    float* out = (float*)d_out;

    prologue_kernel<<<512, 256>>>(pred, targ);
    patchcrps_kernel<<<NBLKM, 256>>>();
    finalize_kernel<<<1, 512>>>(out);
}

// round 11
// speedup vs baseline: 1.0171x; 1.0171x over previous
#include <cuda_runtime.h>

// ---------------------------------------------------------------------------
// PatchCRPS:  mean( (sort(unfold9(pred - avg9(pred))) -
//                    sort(unfold9(targ - avg9(targ))))^2 )
// Shapes: (8,1,256,256) fp32.  K=9, P=4, count_include_pad=False.
//
// R11: deconfound R10. sort9 back to pure FMNMX (latency-bound, ce_fma hurt);
// merge keeps dual-pipe CE at f=1/4 (throughput-bound, model-endorsed).
// ---------------------------------------------------------------------------

#define B 8
#define H 256
#define W 256
#define NPIX (B * H * W)           // 524288
#define NBLKM (2 * B * H)          // 4096 main blocks (half-row each)
#define NTOT 42467328.0            // B*H*W*81

// Scratch (device globals — no allocation)
__device__ float g_dist[2][NPIX];      // x - avgpool9(x)
__device__ float g_partial[NBLKM];     // per-block partial sums

// ---------------------------------------------------------------------------
// Compare-exchange, two flavors:
//   alu:  FMNMX pair (2 alu ops)
//   fma:  min,max = (p+q)/2 -/+ |p-q|/2  (~6 fma ops incl. non-folded FABS)
// ---------------------------------------------------------------------------
__device__ __forceinline__ void ce_alu(float& p, float& q) {
    float a = p, b = q;
    p = fminf(a, b);
    q = fmaxf(a, b);
}
__device__ __forceinline__ void ce_fma(float& p, float& q) {
    float a = p, b = q;
    float d  = a - b;                  // FADD
    float hd = d * 0.5f;               // FMUL
    float hs = __fmaf_rn(d, 0.5f, b);  // FFMA = (p+q)/2
    float ad = fabsf(hd);
    p = hs - ad;                       // FADD
    q = hs + ad;                       // FADD
}

// ---------------------------------------------------------------------------
// Column sorter: Batcher network for n=16 pruned to 9 wires (wires>=9 = +inf).
// Latency-bound (short dependent chains) -> pure FMNMX.
// ---------------------------------------------------------------------------
struct Net9 {
    int lo[64]; int hi[64]; int n;
    constexpr Net9() : lo(), hi(), n(0) {
        for (int p = 1; p < 16; p <<= 1)
            for (int k = p; k >= 1; k >>= 1)
                for (int j = k % p; j + k < 16; j += 2 * k)
                    for (int i = 0; i < k; i++) {
                        int a = i + j, b = i + j + k;
                        if (b < 9 && (a / (2 * p)) == (b / (2 * p))) {
                            lo[n] = a; hi[n] = b; n++;
                        }
                    }
    }
};
__device__ constexpr Net9 N9;

template <int I>
__device__ __forceinline__ void apply9(float (&v)[9]) {
    if constexpr (I < N9.n) {
        constexpr int a = N9.lo[I];
        constexpr int b = N9.hi[I];
        ce_alu(v[a], v[b]);
        apply9<I + 1>(v);
    }
}
__device__ __forceinline__ void sort9(float (&v)[9]) { apply9<0>(v); }

// ---------------------------------------------------------------------------
// Merge network: 256-wire Batcher, phases p>=16 only (16-blocks pre-sorted:
// sorted column of 9 + 7x +inf pad; columns 9..15 all +inf). Exact pruning by
// constexpr always-inf simulation: b-inf -> pruned; a-inf -> MOV a<-b.
// Pad wires never read before first write. Result: wires 0..80 sorted.
// ---------------------------------------------------------------------------
struct MergeNet {
    short a[2048]; short b[2048]; short mv[2048]; int n;
    constexpr MergeNet() : a(), b(), mv(), n(0) {
        bool inf[256] = {};
        for (int c = 0; c < 16; c++)
            for (int i = 0; i < 16; i++)
                inf[c * 16 + i] = (c >= 9) || (i >= 9);
        for (int p = 16; p < 256; p <<= 1)
            for (int k = p; k >= 1; k >>= 1)
                for (int j = k % p; j + k < 256; j += 2 * k)
                    for (int i = 0; i < k; i++) {
                        int x = i + j, y = i + j + k;
                        if ((x / (2 * p)) != (y / (2 * p))) continue;
                        if (inf[y]) continue;              // no-op
                        if (inf[x]) {                       // MOV x<-y
                            a[n] = (short)x; b[n] = (short)y; mv[n] = 1; n++;
                            inf[x] = false; inf[y] = true;
                        } else {
                            a[n] = (short)x; b[n] = (short)y; mv[n] = 0; n++;
                        }
                    }
    }
};
__device__ constexpr MergeNet MN;

template <int I, int T>
__device__ __forceinline__ void mergeChunk(float (&v)[144]) {
    if constexpr (T > 0 && I < MN.n) {
        constexpr int x = MN.a[I];
        constexpr int y = MN.b[I];
        if constexpr (MN.mv[I] != 0) {
            v[x] = v[y];
        } else if constexpr ((I % 4) == 0) {
            ce_fma(v[x], v[y]);
        } else {
            ce_alu(v[x], v[y]);
        }
        mergeChunk<I + 1, T - 1>(v);
    }
}
template <int I>
__device__ __forceinline__ void mergeAll(float (&v)[144]) {
    if constexpr (I < MN.n) {
        mergeChunk<I, 32>(v);
        mergeAll<I + 32>(v);
    }
}
__device__ __forceinline__ void merge81(float (&v)[144]) { mergeAll<0>(v); }

// ---------------------------------------------------------------------------
// Fused prologue: block = (tensor, batch, 8-row strip). Loads 16 rows (with
// halo) into SMEM, 16 rows of horizontal 9-sums, then 8 rows of
// dist = x - boxsum/validcount straight to g_dist. 33 KB SMEM, 512 blocks.
// ---------------------------------------------------------------------------
__global__ __launch_bounds__(256) void prologue_kernel(
        const float* __restrict__ pred, const float* __restrict__ targ) {
    __shared__ float raw[16][264];   // 4 zero pad each side
    __shared__ float hs[16][256];    // horizontal 9-sums

    int tid = threadIdx.x;
    int t   = blockIdx.x >> 8;
    int b   = (blockIdx.x >> 5) & 7;
    int s   = blockIdx.x & 31;
    int r0  = s * 8;
    const float* __restrict__ src = t ? targ : pred;
    int ibase = b * 65536;

#pragma unroll
    for (int r = 0; r < 16; r++) {
        int gr = r0 - 4 + r;
        raw[r][tid + 4] = ((unsigned)gr < 256u) ? src[ibase + gr * 256 + tid] : 0.f;
    }
    if (tid < 4) {
#pragma unroll
        for (int r = 0; r < 16; r++) { raw[r][tid] = 0.f; raw[r][260 + tid] = 0.f; }
    }
    __syncthreads();

#pragma unroll
    for (int r = 0; r < 16; r++) {
        float a = 0.f;
#pragma unroll
        for (int i = 0; i < 9; i++) a += raw[r][tid + i];
        hs[r][tid] = a;
    }
    __syncthreads();

    int cw = min(tid + 4, 255) - max(tid - 4, 0) + 1;
#pragma unroll
    for (int k = 0; k < 8; k++) {
        int h  = r0 + k;
        int lr = k + 4;
        float vs = 0.f;
#pragma unroll
        for (int j = -4; j <= 4; j++) vs += hs[lr + j][tid];
        int ch = min(h + 4, 255) - max(h - 4, 0) + 1;
        g_dist[t][ibase + h * 256 + tid] = raw[lr][tid + 4] - vs / (float)(ch * cw);
    }
}

// ---------------------------------------------------------------------------
// Main kernel: block = (batch, row, half). 256 threads: lane pair (2k,2k+1)
// = (pred, targ) of pixel w0+k. Column sorts -> interleaved SMEM -> gather 9
// sorted columns -> merge network -> diff via shfl_xor(1) -> partial store.
// ---------------------------------------------------------------------------
__global__ __launch_bounds__(256, 1) void patchcrps_kernel() {
    __shared__ float scol[9][280];   // interleaved: col c of tensor t at [i][2c+t]
    __shared__ float ws[8];

    int tid = threadIdx.x;
    int t   = tid & 1;               // 0=pred, 1=targ
    int wl  = tid >> 1;              // 0..127 pixel-in-half
    int r   = blockIdx.x & 1;
    int h   = (blockIdx.x >> 1) & 255;
    int b   = blockIdx.x >> 9;
    int w0  = r * 128;
    int ibase = b * 65536;

    const float* __restrict__ src = g_dist[t];

    // ---- 1. column sorts: thread tid -> (t, c=wl); tid<16 also c=128+wl ----
    {
        float col[9];
        int wc = w0 - 4 + wl;
        bool cv = (unsigned)wc < 256u;
#pragma unroll
        for (int i = 0; i < 9; i++) {
            int hh = h - 4 + i;
            col[i] = (cv && (unsigned)hh < 256u) ? src[ibase + hh * 256 + wc] : 0.f;
        }
        sort9(col);
#pragma unroll
        for (int i = 0; i < 9; i++) scol[i][tid] = col[i];
    }
    if (tid < 16) {
        float col[9];
        int wc = w0 + 124 + wl;      // columns w0+124..w0+131
        bool cv = (unsigned)wc < 256u;
#pragma unroll
        for (int i = 0; i < 9; i++) {
            int hh = h - 4 + i;
            col[i] = (cv && (unsigned)hh < 256u) ? src[ibase + hh * 256 + wc] : 0.f;
        }
        sort9(col);
#pragma unroll
        for (int i = 0; i < 9; i++) scol[i][256 + tid] = col[i];
    }
    __syncthreads();

    // ---- 2. gather 9 sorted columns into 16-spaced wires (conflict-free) ----
    float v[144];
#pragma unroll
    for (int dx = 0; dx < 9; dx++)
#pragma unroll
        for (int i = 0; i < 9; i++)
            v[dx * 16 + i] = scol[i][tid + 2 * dx];

    // ---- 3. merge: sorted 81 ends in wires 0..80 ----
    merge81(v);

    // ---- 4. sorted diff via pair shuffle; both lanes accumulate same d^2 ----
    float acc = 0.f;
#pragma unroll
    for (int i = 0; i < 81; i++) {
        float o = __shfl_xor_sync(0xffffffffu, v[i], 1);
        float d = v[i] - o;
        acc += d * d;
    }

    // ---- 5. block reduction (deterministic) + partial store; exit ----
#pragma unroll
    for (int off = 16; off; off >>= 1)
        acc += __shfl_xor_sync(0xffffffffu, acc, off);
    if ((tid & 31) == 0) ws[tid >> 5] = acc;
    __syncthreads();
    if (tid == 0) {
        float s = 0.f;
#pragma unroll
        for (int k = 0; k < 8; k++) s += ws[k];
        g_partial[blockIdx.x] = s;
    }
}

// ---------------------------------------------------------------------------
// Finalize: fixed-order double reduction of 4096 partials (1 block).
// ---------------------------------------------------------------------------
__global__ __launch_bounds__(512) void finalize_kernel(float* __restrict__ out) {
    __shared__ double sh[512];
    int tid = threadIdx.x;
    double s = 0.0;
#pragma unroll
    for (int e = 0; e < 8; e++) s += (double)g_partial[tid * 8 + e];
    sh[tid] = s;
    __syncthreads();
    for (int off = 256; off; off >>= 1) {
        if (tid < off) sh[tid] += sh[tid + off];
        __syncthreads();
    }
    if (tid == 0) out[0] = (float)(sh[0] / (2.0 * NTOT));
}

// ---------------------------------------------------------------------------
extern "C" void kernel_launch(void* const* d_in, const int* in_sizes, int n_in,
                              void* d_out, int out_size) {
    const float* pred = (const float*)d_in[0];
    const float* targ = (const float*)d_in[1];
    float* out = (float*)d_out;

    prologue_kernel<<<512, 256>>>(pred, targ);
    patchcrps_kernel<<<NBLKM, 256>>>();
    finalize_kernel<<<1, 512>>>(out);
}

// round 12
// speedup vs baseline: 1.0814x; 1.0632x over previous
#include <cuda_runtime.h>

// ---------------------------------------------------------------------------
// PatchCRPS:  mean( (sort(unfold9(pred - avg9(pred))) -
//                    sort(unfold9(targ - avg9(targ))))^2 )
// Shapes: (8,1,256,256) fp32.  K=9, P=4, count_include_pad=False.
//
// R12: R9 CE config (merge f=2/7 dual-pipe, sort9 pure FMNMX) +
//  - shared pair-merges: column pairs (c,c+1) pre-merged to sorted-18 once
//    per block (each reused by 4 pixels); per-pixel merge now p>=32 phases.
//  - two pad launches so ncu (which captures launch idx 3) profiles the
//    main kernel.
// ---------------------------------------------------------------------------

#define B 8
#define H 256
#define W 256
#define NPIX (B * H * W)           // 524288
#define NBLKM (2 * B * H)          // 4096 main blocks (half-row each)
#define NTOT 42467328.0            // B*H*W*81

// Scratch (device globals — no allocation)
__device__ float g_dist[2][NPIX];      // x - avgpool9(x)
__device__ float g_partial[NBLKM];     // per-block partial sums

// ---------------------------------------------------------------------------
// Compare-exchange, two flavors.
// ---------------------------------------------------------------------------
__device__ __forceinline__ void ce_alu(float& p, float& q) {
    float a = p, b = q;
    p = fminf(a, b);
    q = fmaxf(a, b);
}
__device__ __forceinline__ void ce_fma(float& p, float& q) {
    float a = p, b = q;
    float d  = a - b;                  // FADD
    float hd = d * 0.5f;               // FMUL
    float hs = __fmaf_rn(d, 0.5f, b);  // FFMA = (p+q)/2
    float ad = fabsf(hd);
    p = hs - ad;                       // FADD
    q = hs + ad;                       // FADD
}

// ---------------------------------------------------------------------------
// Column sorter: Batcher n=16 pruned to 9 wires. Pure FMNMX (latency-bound).
// ---------------------------------------------------------------------------
struct Net9 {
    int lo[64]; int hi[64]; int n;
    constexpr Net9() : lo(), hi(), n(0) {
        for (int p = 1; p < 16; p <<= 1)
            for (int k = p; k >= 1; k >>= 1)
                for (int j = k % p; j + k < 16; j += 2 * k)
                    for (int i = 0; i < k; i++) {
                        int a = i + j, b = i + j + k;
                        if (b < 9 && (a / (2 * p)) == (b / (2 * p))) {
                            lo[n] = a; hi[n] = b; n++;
                        }
                    }
    }
};
__device__ constexpr Net9 N9;

template <int I>
__device__ __forceinline__ void apply9(float (&v)[9]) {
    if constexpr (I < N9.n) {
        ce_alu(v[N9.lo[I]], v[N9.hi[I]]);
        apply9<I + 1>(v);
    }
}
__device__ __forceinline__ void sort9(float (&v)[9]) { apply9<0>(v); }

// ---------------------------------------------------------------------------
// Pair-merge net: 32 wires, two sorted 16-blocks (9 finite each at 0..8 and
// 16..24), Batcher merge phase p=16. Inf-pruned; result sorted-18 at 0..17.
// ---------------------------------------------------------------------------
struct PairNet {
    short a[64]; short b[64]; short mv[64]; int n;
    constexpr PairNet() : a(), b(), mv(), n(0) {
        bool inf[32] = {};
        for (int i = 0; i < 32; i++) inf[i] = ((i % 16) >= 9);
        for (int p = 16; p < 32; p <<= 1)
            for (int k = p; k >= 1; k >>= 1)
                for (int j = k % p; j + k < 32; j += 2 * k)
                    for (int i = 0; i < k; i++) {
                        int x = i + j, y = i + j + k;
                        if ((x / (2 * p)) != (y / (2 * p))) continue;
                        if (inf[y]) continue;
                        if (inf[x]) {
                            a[n] = (short)x; b[n] = (short)y; mv[n] = 1; n++;
                            inf[x] = false; inf[y] = true;
                        } else {
                            a[n] = (short)x; b[n] = (short)y; mv[n] = 0; n++;
                        }
                    }
    }
};
__device__ constexpr PairNet PN;

template <int I>
__device__ __forceinline__ void applyPair(float (&u)[32]) {
    if constexpr (I < PN.n) {
        constexpr int x = PN.a[I];
        constexpr int y = PN.b[I];
        if constexpr (PN.mv[I] != 0) u[x] = u[y];
        else                         ce_alu(u[x], u[y]);
        applyPair<I + 1>(u);
    }
}

// ---------------------------------------------------------------------------
// Main merge net: 256 wires, blocks at 32-spacing: blocks 0-3 = sorted-18
// (wires 32j+0..17), block 4 = sorted-9 (wires 128..136), rest inf.
// Phases p>=32 only (32-blocks pre-sorted). Inf-pruned. Result: 0..80 sorted.
// ---------------------------------------------------------------------------
struct MergeNet2 {
    short a[2048]; short b[2048]; short mv[2048]; int n;
    constexpr MergeNet2() : a(), b(), mv(), n(0) {
        bool inf[256] = {};
        for (int w = 0; w < 256; w++) {
            int blk = w / 32, off = w % 32;
            bool fin = (blk < 4 && off < 18) || (blk == 4 && off < 9);
            inf[w] = !fin;
        }
        for (int p = 32; p < 256; p <<= 1)
            for (int k = p; k >= 1; k >>= 1)
                for (int j = k % p; j + k < 256; j += 2 * k)
                    for (int i = 0; i < k; i++) {
                        int x = i + j, y = i + j + k;
                        if ((x / (2 * p)) != (y / (2 * p))) continue;
                        if (inf[y]) continue;
                        if (inf[x]) {
                            a[n] = (short)x; b[n] = (short)y; mv[n] = 1; n++;
                            inf[x] = false; inf[y] = true;
                        } else {
                            a[n] = (short)x; b[n] = (short)y; mv[n] = 0; n++;
                        }
                    }
    }
};
__device__ constexpr MergeNet2 MN2;

template <int I, int T>
__device__ __forceinline__ void mergeChunk(float (&v)[144]) {
    if constexpr (T > 0 && I < MN2.n) {
        constexpr int x = MN2.a[I];
        constexpr int y = MN2.b[I];
        if constexpr (MN2.mv[I] != 0) {
            v[x] = v[y];
        } else if constexpr ((I % 7) < 2) {
            ce_fma(v[x], v[y]);
        } else {
            ce_alu(v[x], v[y]);
        }
        mergeChunk<I + 1, T - 1>(v);
    }
}
template <int I>
__device__ __forceinline__ void mergeAll(float (&v)[144]) {
    if constexpr (I < MN2.n) {
        mergeChunk<I, 32>(v);
        mergeAll<I + 32>(v);
    }
}
__device__ __forceinline__ void merge81(float (&v)[144]) { mergeAll<0>(v); }

// ---------------------------------------------------------------------------
// Fused prologue (unchanged): 8-row strips, 33 KB SMEM, 512 blocks.
// ---------------------------------------------------------------------------
__global__ __launch_bounds__(256) void prologue_kernel(
        const float* __restrict__ pred, const float* __restrict__ targ) {
    __shared__ float raw[16][264];
    __shared__ float hsm[16][256];

    int tid = threadIdx.x;
    int t   = blockIdx.x >> 8;
    int b   = (blockIdx.x >> 5) & 7;
    int s   = blockIdx.x & 31;
    int r0  = s * 8;
    const float* __restrict__ src = t ? targ : pred;
    int ibase = b * 65536;

#pragma unroll
    for (int r = 0; r < 16; r++) {
        int gr = r0 - 4 + r;
        raw[r][tid + 4] = ((unsigned)gr < 256u) ? src[ibase + gr * 256 + tid] : 0.f;
    }
    if (tid < 4) {
#pragma unroll
        for (int r = 0; r < 16; r++) { raw[r][tid] = 0.f; raw[r][260 + tid] = 0.f; }
    }
    __syncthreads();

#pragma unroll
    for (int r = 0; r < 16; r++) {
        float a = 0.f;
#pragma unroll
        for (int i = 0; i < 9; i++) a += raw[r][tid + i];
        hsm[r][tid] = a;
    }
    __syncthreads();

    int cw = min(tid + 4, 255) - max(tid - 4, 0) + 1;
#pragma unroll
    for (int k = 0; k < 8; k++) {
        int h  = r0 + k;
        int lr = k + 4;
        float vs = 0.f;
#pragma unroll
        for (int j = -4; j <= 4; j++) vs += hsm[lr + j][tid];
        int ch = min(h + 4, 255) - max(h - 4, 0) + 1;
        g_dist[t][ibase + h * 256 + tid] = raw[lr][tid + 4] - vs / (float)(ch * cw);
    }
}

// ---------------------------------------------------------------------------
// Main kernel: block = (batch, row, half). Lane pair (2k,2k+1) = (pred,targ)
// of pixel w0+k.  1) 272 column sorts -> scol.  2) 268 pair merges
// (9+9 -> 18, each reused by 4 pixels) -> pr.  3) per-pixel gather
// 4x18 + 1x9, merge phases p>=32, diff via shfl_xor(1), partial store.
// ---------------------------------------------------------------------------
__global__ __launch_bounds__(256, 1) void patchcrps_kernel() {
    __shared__ float scol[9][280];   // sorted col c' of tensor t at [i][2c'+t]
    __shared__ float pr[18][272];    // sorted pair p  of tensor t at [i][2p+t]
    __shared__ float ws[8];

    int tid = threadIdx.x;
    int t   = tid & 1;               // 0=pred, 1=targ
    int wl  = tid >> 1;              // 0..127 pixel-in-half
    int r   = blockIdx.x & 1;
    int h   = (blockIdx.x >> 1) & 255;
    int b   = blockIdx.x >> 9;
    int w0  = r * 128;
    int ibase = b * 65536;

    const float* __restrict__ src = g_dist[t];

    // ---- 1. column sorts: c' = wl (all threads); c' = 128+(tid>>1) extras ----
    {
        float col[9];
        int wc = w0 - 4 + wl;
        bool cv = (unsigned)wc < 256u;
#pragma unroll
        for (int i = 0; i < 9; i++) {
            int hh = h - 4 + i;
            col[i] = (cv && (unsigned)hh < 256u) ? src[ibase + hh * 256 + wc] : 0.f;
        }
        sort9(col);
#pragma unroll
        for (int i = 0; i < 9; i++) scol[i][tid] = col[i];
    }
    if (tid < 16) {
        float col[9];
        int wc = w0 + 124 + (tid >> 1);   // columns w0+124..w0+131 (c'=128..135)
        bool cv = (unsigned)wc < 256u;
#pragma unroll
        for (int i = 0; i < 9; i++) {
            int hh = h - 4 + i;
            col[i] = (cv && (unsigned)hh < 256u) ? src[ibase + hh * 256 + wc] : 0.f;
        }
        sort9(col);
#pragma unroll
        for (int i = 0; i < 9; i++) scol[i][256 + tid] = col[i];
    }
    __syncthreads();

    // ---- 2. pair merges: p = wl (all threads); p = 128+(tid>>1) extras ----
    {
        float u[32];
#pragma unroll
        for (int i = 0; i < 9; i++) {
            u[i]      = scol[i][tid];
            u[16 + i] = scol[i][tid + 2];
        }
        applyPair<0>(u);
#pragma unroll
        for (int i = 0; i < 18; i++) pr[i][tid] = u[i];
    }
    if (tid < 12) {                       // pairs p=128..133 per tensor
        float u[32];
#pragma unroll
        for (int i = 0; i < 9; i++) {
            u[i]      = scol[i][256 + tid];
            u[16 + i] = scol[i][256 + tid + 2];
        }
        applyPair<0>(u);
#pragma unroll
        for (int i = 0; i < 18; i++) pr[i][256 + tid] = u[i];
    }
    __syncthreads();

    // ---- 3. gather 4 sorted-18 pairs + 1 sorted-9 column (conflict-free) ----
    float v[144];
#pragma unroll
    for (int j = 0; j < 4; j++)
#pragma unroll
        for (int i = 0; i < 18; i++)
            v[32 * j + i] = pr[i][tid + 4 * j];
#pragma unroll
    for (int i = 0; i < 9; i++)
        v[128 + i] = scol[i][tid + 16];

    // ---- 4. merge phases p>=32: sorted 81 ends in wires 0..80 ----
    merge81(v);

    // ---- 5. sorted diff via pair shuffle; both lanes accumulate same d^2 ----
    float acc = 0.f;
#pragma unroll
    for (int i = 0; i < 81; i++) {
        float o = __shfl_xor_sync(0xffffffffu, v[i], 1);
        float d = v[i] - o;
        acc += d * d;
    }

    // ---- 6. block reduction (deterministic) + partial store; exit ----
#pragma unroll
    for (int off = 16; off; off >>= 1)
        acc += __shfl_xor_sync(0xffffffffu, acc, off);
    if ((tid & 31) == 0) ws[tid >> 5] = acc;
    __syncthreads();
    if (tid == 0) {
        float s = 0.f;
#pragma unroll
        for (int k = 0; k < 8; k++) s += ws[k];
        g_partial[blockIdx.x] = s;
    }
}

// ---------------------------------------------------------------------------
// Finalize: fixed-order double reduction of 4096 partials (1 block).
// ---------------------------------------------------------------------------
__global__ __launch_bounds__(512) void finalize_kernel(float* __restrict__ out) {
    __shared__ double sh[512];
    int tid = threadIdx.x;
    double s = 0.0;
#pragma unroll
    for (int e = 0; e < 8; e++) s += (double)g_partial[tid * 8 + e];
    sh[tid] = s;
    __syncthreads();
    for (int off = 256; off; off >>= 1) {
        if (tid < off) sh[tid] += sh[tid + off];
        __syncthreads();
    }
    if (tid == 0) out[0] = (float)(sh[0] / (2.0 * NTOT));
}

// Pads: place patchcrps_kernel at launch index 3 (the one ncu captures).
__global__ void pad_kernel() {}

// ---------------------------------------------------------------------------
extern "C" void kernel_launch(void* const* d_in, const int* in_sizes, int n_in,
                              void* d_out, int out_size) {
    const float* pred = (const float*)d_in[0];
    const float* targ = (const float*)d_in[1];
    float* out = (float*)d_out;

    prologue_kernel<<<512, 256>>>(pred, targ);     // idx 0
    pad_kernel<<<1, 32>>>();                       // idx 1
    pad_kernel<<<1, 32>>>();                       // idx 2
    patchcrps_kernel<<<NBLKM, 256>>>();            // idx 3  <- ncu capture
    finalize_kernel<<<1, 512>>>(out);              // idx 4
}